// round 11
// baseline (speedup 1.0000x reference)
#include <cuda_runtime.h>
#include <cuda_bf16.h>
#include <math.h>
#include <cstdint>

// Problem constants
#define BATCH 4
#define C 128
#define NG 8
#define CPG 16
#define NTOK 4096
#define EPS 1e-5f
#define QSCALE (0.08838834764831845f * 1.4426950408889634f)  // 1/sqrt(C) * log2(e)

// Scratch
__device__ float2        g_part[BATCH * NG * 16];             // partial (sum, sumsq)
__device__ __nv_bfloat16 g_qkv[BATCH * NTOK * 3 * C];         // [m][384] (q pre-scaled)

// ---------------------------------------------------------------------------
// helpers
// ---------------------------------------------------------------------------
__device__ __forceinline__ void mma_bf16(float* d, const uint32_t* a,
                                         uint32_t b0, uint32_t b1) {
    asm volatile(
        "mma.sync.aligned.m16n8k16.row.col.f32.bf16.bf16.f32 "
        "{%0,%1,%2,%3}, {%4,%5,%6,%7}, {%8,%9}, {%0,%1,%2,%3};"
        : "+f"(d[0]), "+f"(d[1]), "+f"(d[2]), "+f"(d[3])
        : "r"(a[0]), "r"(a[1]), "r"(a[2]), "r"(a[3]), "r"(b0), "r"(b1));
}
#define LDSM4(R, A) \
    asm volatile("ldmatrix.sync.aligned.m8n8.x4.shared.b16 {%0,%1,%2,%3}, [%4];" \
        : "=r"((R)[0]), "=r"((R)[1]), "=r"((R)[2]), "=r"((R)[3]) : "r"(A))
#define LDSM4T(R, A) \
    asm volatile("ldmatrix.sync.aligned.m8n8.x4.trans.shared.b16 {%0,%1,%2,%3}, [%4];" \
        : "=r"((R)[0]), "=r"((R)[1]), "=r"((R)[2]), "=r"((R)[3]) : "r"(A))
__device__ __forceinline__ void cp16(uint32_t dst, const void* src) {
    asm volatile("cp.async.ca.shared.global [%0], [%1], 16;" :: "r"(dst), "l"(src));
}
#define CP_COMMIT() asm volatile("cp.async.commit_group;" ::: "memory")
#define CP_WAIT(n)  asm volatile("cp.async.wait_group %0;" :: "n"(n) : "memory")
__device__ __forceinline__ uint32_t pack_bf2(float a, float b) {
    __nv_bfloat162 h = __floats2bfloat162_rn(a, b);
    return *reinterpret_cast<uint32_t*>(&h);
}
__device__ __forceinline__ float ex2f(float x) {
    float r;
    asm("ex2.approx.f32 %0, %1;" : "=f"(r) : "f"(x));
    return r;
}

// ---------------------------------------------------------------------------
// Kernel 1: GroupNorm partial stats. Grid 512 = (bg 32) x (chunk 16).
// ---------------------------------------------------------------------------
__global__ void gn_stats_kernel(const float* __restrict__ x)
{
    int bg = blockIdx.x >> 4, ck = blockIdx.x & 15;
    const float4* xp = (const float4*)(x + (size_t)bg * CPG * NTOK
                                         + (size_t)ck * (CPG * NTOK / 16));
    int t = threadIdx.x;
    float s = 0.f, ss = 0.f;
#pragma unroll
    for (int i = 0; i < 4; i++) {
        float4 v = xp[t + i * 256];
        s  += v.x + v.y + v.z + v.w;
        ss += v.x * v.x + v.y * v.y + v.z * v.z + v.w * v.w;
    }
#pragma unroll
    for (int o = 16; o > 0; o >>= 1) {
        s  += __shfl_xor_sync(0xffffffffu, s, o);
        ss += __shfl_xor_sync(0xffffffffu, ss, o);
    }
    __shared__ float rs[8], rss[8];
    if ((t & 31) == 0) { rs[t >> 5] = s; rss[t >> 5] = ss; }
    __syncthreads();
    if (t == 0) {
        float a = 0.f, b = 0.f;
#pragma unroll
        for (int i = 0; i < 8; i++) { a += rs[i]; b += rss[i]; }
        g_part[blockIdx.x] = make_float2(a, b);
    }
}

// ---------------------------------------------------------------------------
// Kernel 2: fused GroupNorm-normalize + QKV GEMM, bf16 HMMA. (unchanged)
// ---------------------------------------------------------------------------
#define GP 136
#define QKV_SMEM (2 * 128 * GP * 2)    // 69632 B

__global__ __launch_bounds__(256, 1) void qkv_kernel(const float* __restrict__ x,
                                                     const float* __restrict__ gnw,
                                                     const float* __restrict__ gnb,
                                                     const float* __restrict__ W,
                                                     const float* __restrict__ bias)
{
    extern __shared__ __nv_bfloat16 sq[];
    __nv_bfloat16* As = sq;              // [c][m] pitch GP
    __nv_bfloat16* Bs = sq + 128 * GP;   // [o][c] pitch GP
    const uint32_t sbase = (uint32_t)__cvta_generic_to_shared(sq);
    const int tid = threadIdx.x;
    const int w = tid >> 5, lane = tid & 31;
    const int gid = lane >> 2, tig = lane & 3;
    const int m0 = blockIdx.x * 128, o0 = blockIdx.y * 128;
    const int b = m0 >> 12, n0 = m0 & 4095;

    __shared__ float stats[16];
    if (tid < 8) {
        float s = 0.f, ss = 0.f;
#pragma unroll
        for (int ck = 0; ck < 16; ck++) {
            float2 p = g_part[(b * NG + tid) * 16 + ck];
            s += p.x; ss += p.y;
        }
        float mean = s * (1.f / (CPG * NTOK));
        float var  = ss * (1.f / (CPG * NTOK)) - mean * mean;
        stats[tid * 2]     = mean;
        stats[tid * 2 + 1] = rsqrtf(var + EPS);
    }
    __syncthreads();

    for (int i = tid; i < 128 * 32; i += 256) {
        int c = i >> 5, n4 = (i & 31) << 2;
        float4 v = *(const float4*)(x + ((size_t)b * C + c) * NTOK + n0 + n4);
        int g = c >> 4;
        float a = stats[g * 2 + 1] * gnw[c];
        float bb = gnb[c] - stats[g * 2] * a;
        *(uint32_t*)(As + c * GP + n4)     = pack_bf2(v.x * a + bb, v.y * a + bb);
        *(uint32_t*)(As + c * GP + n4 + 2) = pack_bf2(v.z * a + bb, v.w * a + bb);
    }
    for (int i = tid; i < 128 * 32; i += 256) {
        int r = i >> 5, c4 = (i & 31) << 2;
        float4 v = *(const float4*)(W + (size_t)(o0 + r) * C + c4);
        *(uint32_t*)(Bs + r * GP + c4)     = pack_bf2(v.x, v.y);
        *(uint32_t*)(Bs + r * GP + c4 + 2) = pack_bf2(v.z, v.w);
    }
    __syncthreads();

    const int l15 = lane & 15;
    const int hi8 = (lane >> 4) << 3;
    const int arow = (lane & 7) + ((lane >> 4) << 3);
    const int acol = ((lane >> 3) & 1) << 3;
    const uint32_t aA = sbase + (arow * GP + w * 16 + acol) * 2;
    const uint32_t aB = sbase + (128 * GP + l15 * GP + hi8) * 2;

    float acc[16][4];
#pragma unroll
    for (int i = 0; i < 16; i++)
#pragma unroll
        for (int j = 0; j < 4; j++) acc[i][j] = 0.f;

#pragma unroll
    for (int kk = 0; kk < 8; kk++) {
        const int k0 = kk * 16;
        uint32_t aq[4];
        LDSM4T(aq, aA + k0 * GP * 2);
#pragma unroll
        for (int ntp = 0; ntp < 8; ntp++) {
            uint32_t bk[4];
            LDSM4(bk, aB + (ntp * 16 * GP + k0) * 2);
            mma_bf16(acc[2 * ntp],     aq, bk[0], bk[2]);
            mma_bf16(acc[2 * ntp + 1], aq, bk[1], bk[3]);
        }
    }
    __syncthreads();

    const float sc = (o0 == 0) ? QSCALE : 1.f;
    const int ml = w * 16 + gid;
#pragma unroll
    for (int nt = 0; nt < 16; nt++) {
        int o = nt * 8 + 2 * tig;
        float b0 = bias[o0 + o], b1 = bias[o0 + o + 1];
        *(uint32_t*)(As + ml * GP + o) =
            pack_bf2((acc[nt][0] + b0) * sc, (acc[nt][1] + b1) * sc);
        *(uint32_t*)(As + (ml + 8) * GP + o) =
            pack_bf2((acc[nt][2] + b0) * sc, (acc[nt][3] + b1) * sc);
    }
    __syncthreads();

    for (int i = tid; i < 128 * 16; i += 256) {
        int r = i >> 4, c8 = (i & 15) << 3;
        *(uint4*)(g_qkv + (size_t)(m0 + r) * 384 + o0 + c8) =
            *(const uint4*)(As + r * GP + c8);
    }
}

// ---------------------------------------------------------------------------
// Kernel 3: flash attention, TQ=64, 2 CTAs/SM, key-split warpgroups.
// Warps 0-3: keys 0-31 of each tile; warps 4-7: keys 32-63. Partial O/l
// merged in epilogue (no-rescale softmax => pure sums). Fused proj+residual.
// ---------------------------------------------------------------------------
#define TQ 64
#define TKEY 64
#define QP 136
#define KS (TQ * QP)                       // Q region: 8704 elems
#define STAGE (2 * TKEY * QP)              // K+V per stage: 17408 elems
#define VS_REL (TKEY * QP)
#define LS_OFF (KS + 2 * STAGE)            // lsum at elem 43520
#define ATTN_SMEM (LS_OFF * 2 + 256)       // 87296 B  -> 2 CTAs/SM
#define ST0_B ((KS) * 2)                   // stage0 byte offset (W region)
#define ST1_B ((KS + STAGE) * 2)           // stage1 byte offset (merge/proj buf)
#define OMP 132                            // merge buffer fp32 pitch
#define PFP 68                             // proj fp32 pitch

__global__ __launch_bounds__(256, 2) void attn_kernel(const float* __restrict__ pw,
                                                      const float* __restrict__ pb,
                                                      const float* __restrict__ x,
                                                      float* __restrict__ y)
{
    extern __shared__ __nv_bfloat16 sb[];
    const uint32_t sbase = (uint32_t)__cvta_generic_to_shared(sb);
    const int tid = threadIdx.x;
    const int w = tid >> 5, lane = tid & 31;
    const int gid = lane >> 2, tig = lane & 3;
    const int wq = w & 3;                    // q-tile warp index
    const int grp = w >> 2;                  // key-half group (0 or 1)
    const int kh = grp << 5;                 // key offset within tile
    const int qrow = wq * 16 + gid;
    const int b = blockIdx.y;
    const int n0 = blockIdx.x * TQ;
    const __nv_bfloat16* Qb = g_qkv + (size_t)b * NTOK * 384;

    auto issueKV = [&](int jt, int s) {
        const int j0 = jt * TKEY;
        const uint32_t base = sbase + (KS + s * STAGE) * 2;
#pragma unroll
        for (int it = 0; it < 8; it++) {
            int i = tid + it * 256;
            int kv = i >> 10;
            int r = (i >> 4) & 63;
            int c8 = (i & 15) << 3;
            cp16(base + (kv * VS_REL + r * QP + c8) * 2,
                 Qb + (size_t)(j0 + r) * 384 + 128 + (kv << 7) + c8);
        }
    };

    issueKV(0, 0);
    CP_COMMIT();

    // Q tile (64 rows), overlapped with first cp.async
    for (int i = tid; i < TQ * 16; i += 256) {
        int r = i >> 4, c8 = (i & 15) << 3;
        *(uint4*)(sb + r * QP + c8) = *(const uint4*)(Qb + (size_t)(n0 + r) * 384 + c8);
    }

    const int l15 = lane & 15;
    const int hi8 = (lane >> 4) << 3;
    const uint32_t aQ = sbase + ((wq * 16 + l15) * QP + hi8) * 2;
    const int vrow = (lane & 7) + ((lane >> 3) & 1) * 8;

    float oacc[16][4];
#pragma unroll
    for (int i = 0; i < 16; i++)
#pragma unroll
        for (int j = 0; j < 4; j++) oacc[i][j] = 0.f;
    float l0 = 0.f, l1 = 0.f;

    const int NT = NTOK / TKEY;
    for (int jt = 0; jt < NT; jt++) {
        const int s = jt & 1;
        CP_WAIT(0);
        __syncthreads();                     // stage s ready; stage s^1 retired
        if (jt + 1 < NT) {
            issueKV(jt + 1, s ^ 1);
            CP_COMMIT();
        }

        const uint32_t aK = sbase + (KS + s * STAGE + (kh + l15) * QP + hi8) * 2;
        const uint32_t aV = sbase + (KS + s * STAGE + VS_REL + (kh + vrow) * QP + hi8) * 2;

        // ---- S = Q K^T for this warp's 32-key half ----
        float sacc[4][4];
#pragma unroll
        for (int i = 0; i < 4; i++)
#pragma unroll
            for (int j = 0; j < 4; j++) sacc[i][j] = 0.f;

#pragma unroll
        for (int kk = 0; kk < 8; kk++) {
            const int k0 = kk * 16;
            uint32_t aq[4];
            LDSM4(aq, aQ + k0 * 2);
#pragma unroll
            for (int ntp = 0; ntp < 2; ntp++) {
                uint32_t bk[4];
                LDSM4(bk, aK + (ntp * 16 * QP + k0) * 2);
                mma_bf16(sacc[2 * ntp],     aq, bk[0], bk[2]);
                mma_bf16(sacc[2 * ntp + 1], aq, bk[1], bk[3]);
            }
        }

        // ---- softmax (ex2) interleaved with O-MMA over the 32-key half ----
#pragma unroll
        for (int kk = 0; kk < 2; kk++) {
            uint32_t ap[4];
            {
                float p0 = ex2f(sacc[2 * kk][0]);
                float p1 = ex2f(sacc[2 * kk][1]);
                float p2 = ex2f(sacc[2 * kk][2]);
                float p3 = ex2f(sacc[2 * kk][3]);
                l0 += p0 + p1; l1 += p2 + p3;
                ap[0] = pack_bf2(p0, p1);
                ap[1] = pack_bf2(p2, p3);
                float q0 = ex2f(sacc[2 * kk + 1][0]);
                float q1 = ex2f(sacc[2 * kk + 1][1]);
                float q2 = ex2f(sacc[2 * kk + 1][2]);
                float q3 = ex2f(sacc[2 * kk + 1][3]);
                l0 += q0 + q1; l1 += q2 + q3;
                ap[2] = pack_bf2(q0, q1);
                ap[3] = pack_bf2(q2, q3);
            }
            const int k0 = kk * 16;
#pragma unroll
            for (int ccp = 0; ccp < 8; ccp++) {
                uint32_t bv[4];
                LDSM4T(bv, aV + (k0 * QP + ccp * 16) * 2);
                mma_bf16(oacc[2 * ccp],     ap, bv[0], bv[1]);
                mma_bf16(oacc[2 * ccp + 1], ap, bv[2], bv[3]);
            }
        }
    }
    __syncthreads();   // all compute done; both stages retired

    // quad-reduce l (rows are per-quad)
    l0 += __shfl_xor_sync(0xffffffffu, l0, 1);
    l0 += __shfl_xor_sync(0xffffffffu, l0, 2);
    l1 += __shfl_xor_sync(0xffffffffu, l1, 1);
    l1 += __shfl_xor_sync(0xffffffffu, l1, 2);

    // load W_proj bf16 into retired stage0
    __nv_bfloat16* Ws = sb + KS;
    for (int i = tid; i < 128 * 32; i += 256) {
        int r = i >> 5, c4 = (i & 31) << 2;
        float4 v = *(const float4*)(pw + (size_t)r * C + c4);
        *(uint32_t*)(Ws + r * GP + c4)     = pack_bf2(v.x, v.y);
        *(uint32_t*)(Ws + r * GP + c4 + 2) = pack_bf2(v.z, v.w);
    }

    // group A dumps partial O (fp32) + l into stage1 / lsum
    float* Om   = (float*)((char*)sb + ST1_B);     // [q][c] pitch OMP
    float* lsum = (float*)(sb + LS_OFF);           // 64 floats
    if (grp == 0) {
#pragma unroll
        for (int nt = 0; nt < 16; nt++) {
            int col = nt * 8 + 2 * tig;
            Om[qrow * OMP + col]           = oacc[nt][0];
            Om[qrow * OMP + col + 1]       = oacc[nt][1];
            Om[(qrow + 8) * OMP + col]     = oacc[nt][2];
            Om[(qrow + 8) * OMP + col + 1] = oacc[nt][3];
        }
        if (tig == 0) { lsum[qrow] = l0; lsum[qrow + 8] = l1; }
    }
    __syncthreads();

    // group B merges, normalizes, writes bf16 O into Q region
    if (grp == 1) {
        float inv0 = 1.f / (l0 + lsum[qrow]);
        float inv1 = 1.f / (l1 + lsum[qrow + 8]);
#pragma unroll
        for (int nt = 0; nt < 16; nt++) {
            int col = nt * 8 + 2 * tig;
            float o0 = (Om[qrow * OMP + col]           + oacc[nt][0]) * inv0;
            float o1 = (Om[qrow * OMP + col + 1]       + oacc[nt][1]) * inv0;
            float o2 = (Om[(qrow + 8) * OMP + col]     + oacc[nt][2]) * inv1;
            float o3 = (Om[(qrow + 8) * OMP + col + 1] + oacc[nt][3]) * inv1;
            *(uint32_t*)(sb + qrow * QP + col)       = pack_bf2(o0, o1);
            *(uint32_t*)(sb + (qrow + 8) * QP + col) = pack_bf2(o2, o3);
        }
    }
    __syncthreads();

    // fused proj: each warp does 16 q-rows x 64 o-cols
    const int colh = grp << 6;                         // 0 or 64
    const uint32_t aO = aQ;                            // O lives in Q region
    const uint32_t aW = sbase + ST0_B + ((colh + l15) * GP + hi8) * 2;

    float acc[8][4];
#pragma unroll
    for (int i = 0; i < 8; i++)
#pragma unroll
        for (int j = 0; j < 4; j++) acc[i][j] = 0.f;

#pragma unroll
    for (int kk = 0; kk < 8; kk++) {
        const int k0 = kk * 16;
        uint32_t aq[4];
        LDSM4(aq, aO + k0 * 2);
#pragma unroll
        for (int ntp = 0; ntp < 4; ntp++) {
            uint32_t bk[4];
            LDSM4(bk, aW + (ntp * 16 * GP + k0) * 2);
            mma_bf16(acc[2 * ntp],     aq, bk[0], bk[2]);
            mma_bf16(acc[2 * ntp + 1], aq, bk[1], bk[3]);
        }
    }
    __syncthreads();   // Om reads done; stage1 reusable for proj result

    // stage proj fp32 [o][n] into stage1
    float* Pf = (float*)((char*)sb + ST1_B);   // [o:128][n:64] pitch PFP
    const int nl = wq * 16 + gid;
#pragma unroll
    for (int nt = 0; nt < 8; nt++) {
        int o = colh + nt * 8 + 2 * tig;
        Pf[o * PFP + nl]           = acc[nt][0];
        Pf[(o + 1) * PFP + nl]     = acc[nt][1];
        Pf[o * PFP + nl + 8]       = acc[nt][2];
        Pf[(o + 1) * PFP + nl + 8] = acc[nt][3];
    }
    __syncthreads();

    // coalesced residual add + store
    for (int i = tid; i < 128 * 16; i += 256) {
        int o = i >> 4, n4 = (i & 15) << 2;
        size_t gaddr = ((size_t)b * C + o) * NTOK + n0 + n4;
        float4 xv = *(const float4*)(x + gaddr);
        float4 ov = *(const float4*)(Pf + o * PFP + n4);
        float bo = pb[o];
        float4 r = make_float4(xv.x + ov.x + bo, xv.y + ov.y + bo,
                               xv.z + ov.z + bo, xv.w + ov.w + bo);
        *(float4*)(y + gaddr) = r;
    }
}

// ---------------------------------------------------------------------------
extern "C" void kernel_launch(void* const* d_in, const int* in_sizes, int n_in,
                              void* d_out, int out_size)
{
    const float* x     = (const float*)d_in[0];
    const float* gn_w  = (const float*)d_in[1];
    const float* gn_b  = (const float*)d_in[2];
    const float* qkv_w = (const float*)d_in[3];
    const float* qkv_b = (const float*)d_in[4];
    const float* pr_w  = (const float*)d_in[5];
    const float* pr_b  = (const float*)d_in[6];
    float* y = (float*)d_out;

    cudaFuncSetAttribute(qkv_kernel,  cudaFuncAttributeMaxDynamicSharedMemorySize, QKV_SMEM);
    cudaFuncSetAttribute(attn_kernel, cudaFuncAttributeMaxDynamicSharedMemorySize, ATTN_SMEM);

    gn_stats_kernel<<<BATCH * NG * 16, 256>>>(x);
    qkv_kernel<<<dim3((BATCH * NTOK) / 128, 3), 256, QKV_SMEM>>>(x, gn_w, gn_b, qkv_w, qkv_b);
    attn_kernel<<<dim3(NTOK / TQ, BATCH), 256, ATTN_SMEM>>>(pr_w, pr_b, x, y);
}

// round 12
// speedup vs baseline: 1.1619x; 1.1619x over previous
#include <cuda_runtime.h>
#include <cuda_bf16.h>
#include <math.h>
#include <cstdint>

// Problem constants
#define BATCH 4
#define C 128
#define NG 8
#define CPG 16
#define NTOK 4096
#define EPS 1e-5f
#define QSCALE (0.08838834764831845f * 1.4426950408889634f)  // 1/sqrt(C) * log2(e)

// Scratch
__device__ float2        g_part[BATCH * NG * 16];             // partial (sum, sumsq)
__device__ __nv_bfloat16 g_q[BATCH * NTOK * C];               // [m][128] (pre-scaled)
__device__ unsigned char g_kv[BATCH * 64 * 32768];            // swizzled 32KB K/V tiles

// ---------------------------------------------------------------------------
// helpers
// ---------------------------------------------------------------------------
__device__ __forceinline__ void mma_bf16(float* d, const uint32_t* a,
                                         uint32_t b0, uint32_t b1) {
    asm volatile(
        "mma.sync.aligned.m16n8k16.row.col.f32.bf16.bf16.f32 "
        "{%0,%1,%2,%3}, {%4,%5,%6,%7}, {%8,%9}, {%0,%1,%2,%3};"
        : "+f"(d[0]), "+f"(d[1]), "+f"(d[2]), "+f"(d[3])
        : "r"(a[0]), "r"(a[1]), "r"(a[2]), "r"(a[3]), "r"(b0), "r"(b1));
}
#define LDSM4(R, A) \
    asm volatile("ldmatrix.sync.aligned.m8n8.x4.shared.b16 {%0,%1,%2,%3}, [%4];" \
        : "=r"((R)[0]), "=r"((R)[1]), "=r"((R)[2]), "=r"((R)[3]) : "r"(A))
#define LDSM4T(R, A) \
    asm volatile("ldmatrix.sync.aligned.m8n8.x4.trans.shared.b16 {%0,%1,%2,%3}, [%4];" \
        : "=r"((R)[0]), "=r"((R)[1]), "=r"((R)[2]), "=r"((R)[3]) : "r"(A))
__device__ __forceinline__ uint32_t pack_bf2(float a, float b) {
    __nv_bfloat162 h = __floats2bfloat162_rn(a, b);
    return *reinterpret_cast<uint32_t*>(&h);
}
__device__ __forceinline__ float ex2f(float x) {
    float r;
    asm("ex2.approx.f32 %0, %1;" : "=f"(r) : "f"(x));
    return r;
}
// bulk async copy gmem->smem with mbarrier completion (sm_90 PTX)
__device__ __forceinline__ void bulkcp(uint32_t dst, const void* src,
                                       uint32_t bytes, uint32_t mbar) {
    asm volatile(
        "cp.async.bulk.shared::cta.global.mbarrier::complete_tx::bytes "
        "[%0], [%1], %2, [%3];"
        :: "r"(dst), "l"(src), "r"(bytes), "r"(mbar) : "memory");
}
#define MBAR_INIT(a, n) \
    asm volatile("mbarrier.init.shared.b64 [%0], %1;" :: "r"(a), "r"(n) : "memory")
#define MBAR_EXPECT_TX(a, n) \
    asm volatile("mbarrier.arrive.expect_tx.shared.b64 _, [%0], %1;" \
                 :: "r"(a), "r"(n) : "memory")
#define MBAR_WAIT(addr, parity) do { \
    asm volatile("{\n\t.reg .pred P1;\n\t" \
        "WAIT_%=:\n\t" \
        "mbarrier.try_wait.parity.acquire.cta.shared::cta.b64 P1, [%0], %1, 0x989680;\n\t" \
        "@P1 bra.uni DONE_%=;\n\t" \
        "bra.uni WAIT_%=;\n\t" \
        "DONE_%=:\n\t}" \
        :: "r"(addr), "r"(parity) : "memory"); \
} while (0)

// ---------------------------------------------------------------------------
// Kernel 1: GroupNorm partial stats. Grid 512 = (bg 32) x (chunk 16).
// ---------------------------------------------------------------------------
__global__ void gn_stats_kernel(const float* __restrict__ x)
{
    int bg = blockIdx.x >> 4, ck = blockIdx.x & 15;
    const float4* xp = (const float4*)(x + (size_t)bg * CPG * NTOK
                                         + (size_t)ck * (CPG * NTOK / 16));
    int t = threadIdx.x;
    float s = 0.f, ss = 0.f;
#pragma unroll
    for (int i = 0; i < 4; i++) {
        float4 v = xp[t + i * 256];
        s  += v.x + v.y + v.z + v.w;
        ss += v.x * v.x + v.y * v.y + v.z * v.z + v.w * v.w;
    }
#pragma unroll
    for (int o = 16; o > 0; o >>= 1) {
        s  += __shfl_xor_sync(0xffffffffu, s, o);
        ss += __shfl_xor_sync(0xffffffffu, ss, o);
    }
    __shared__ float rs[8], rss[8];
    if ((t & 31) == 0) { rs[t >> 5] = s; rss[t >> 5] = ss; }
    __syncthreads();
    if (t == 0) {
        float a = 0.f, b = 0.f;
#pragma unroll
        for (int i = 0; i < 8; i++) { a += rs[i]; b += rss[i]; }
        g_part[blockIdx.x] = make_float2(a, b);
    }
}

// ---------------------------------------------------------------------------
// Kernel 2: fused GroupNorm-normalize + QKV GEMM, bf16 HMMA.
// Grid (128 m-tiles, 3 o-blocks). Q -> g_q; K/V -> g_kv pre-swizzled tiles.
// ---------------------------------------------------------------------------
#define GP 136
#define QKV_SMEM (2 * 128 * GP * 2)    // 69632 B

__global__ __launch_bounds__(256, 1) void qkv_kernel(const float* __restrict__ x,
                                                     const float* __restrict__ gnw,
                                                     const float* __restrict__ gnb,
                                                     const float* __restrict__ W,
                                                     const float* __restrict__ bias)
{
    extern __shared__ __nv_bfloat16 sq[];
    __nv_bfloat16* As = sq;              // [c][m] pitch GP
    __nv_bfloat16* Bs = sq + 128 * GP;   // [o][c] pitch GP
    const uint32_t sbase = (uint32_t)__cvta_generic_to_shared(sq);
    const int tid = threadIdx.x;
    const int w = tid >> 5, lane = tid & 31;
    const int gid = lane >> 2, tig = lane & 3;
    const int m0 = blockIdx.x * 128, o0 = blockIdx.y * 128;
    const int bat = m0 >> 12, n0 = m0 & 4095;

    __shared__ float stats[16];
    if (tid < 8) {
        float s = 0.f, ss = 0.f;
#pragma unroll
        for (int ck = 0; ck < 16; ck++) {
            float2 p = g_part[(bat * NG + tid) * 16 + ck];
            s += p.x; ss += p.y;
        }
        float mean = s * (1.f / (CPG * NTOK));
        float var  = ss * (1.f / (CPG * NTOK)) - mean * mean;
        stats[tid * 2]     = mean;
        stats[tid * 2 + 1] = rsqrtf(var + EPS);
    }
    __syncthreads();

    for (int i = tid; i < 128 * 32; i += 256) {
        int c = i >> 5, n4 = (i & 31) << 2;
        float4 v = *(const float4*)(x + ((size_t)bat * C + c) * NTOK + n0 + n4);
        int g = c >> 4;
        float a = stats[g * 2 + 1] * gnw[c];
        float bb = gnb[c] - stats[g * 2] * a;
        *(uint32_t*)(As + c * GP + n4)     = pack_bf2(v.x * a + bb, v.y * a + bb);
        *(uint32_t*)(As + c * GP + n4 + 2) = pack_bf2(v.z * a + bb, v.w * a + bb);
    }
    for (int i = tid; i < 128 * 32; i += 256) {
        int r = i >> 5, c4 = (i & 31) << 2;
        float4 v = *(const float4*)(W + (size_t)(o0 + r) * C + c4);
        *(uint32_t*)(Bs + r * GP + c4)     = pack_bf2(v.x, v.y);
        *(uint32_t*)(Bs + r * GP + c4 + 2) = pack_bf2(v.z, v.w);
    }
    __syncthreads();

    const int l15 = lane & 15;
    const int hi8 = (lane >> 4) << 3;
    const int arow = (lane & 7) + ((lane >> 4) << 3);
    const int acol = ((lane >> 3) & 1) << 3;
    const uint32_t aA = sbase + (arow * GP + w * 16 + acol) * 2;
    const uint32_t aB = sbase + (128 * GP + l15 * GP + hi8) * 2;

    float acc[16][4];
#pragma unroll
    for (int i = 0; i < 16; i++)
#pragma unroll
        for (int j = 0; j < 4; j++) acc[i][j] = 0.f;

#pragma unroll
    for (int kk = 0; kk < 8; kk++) {
        const int k0 = kk * 16;
        uint32_t aq[4];
        LDSM4T(aq, aA + k0 * GP * 2);
#pragma unroll
        for (int ntp = 0; ntp < 8; ntp++) {
            uint32_t bk[4];
            LDSM4(bk, aB + (ntp * 16 * GP + k0) * 2);
            mma_bf16(acc[2 * ntp],     aq, bk[0], bk[2]);
            mma_bf16(acc[2 * ntp + 1], aq, bk[1], bk[3]);
        }
    }
    __syncthreads();

    // stage result bf16 into As region: [m_local][o_local] pitch GP
    const float sc = (o0 == 0) ? QSCALE : 1.f;
    const int ml = w * 16 + gid;
#pragma unroll
    for (int nt = 0; nt < 16; nt++) {
        int o = nt * 8 + 2 * tig;
        float b0 = bias[o0 + o], b1 = bias[o0 + o + 1];
        *(uint32_t*)(As + ml * GP + o) =
            pack_bf2((acc[nt][0] + b0) * sc, (acc[nt][1] + b1) * sc);
        *(uint32_t*)(As + (ml + 8) * GP + o) =
            pack_bf2((acc[nt][2] + b0) * sc, (acc[nt][3] + b1) * sc);
    }
    __syncthreads();

    if (o0 == 0) {
        // Q: coalesced write, [m][128] contiguous
        for (int i = tid; i < 128 * 16; i += 256) {
            int r = i >> 4, c8 = (i & 15) << 3;
            *(uint4*)(g_q + (size_t)(m0 + r) * C + c8) =
                *(const uint4*)(As + r * GP + c8);
        }
    } else {
        // K/V: write swizzled tile images (sector-coalesced: 16B chunks stay
        // inside their 128B row)
        const int kv = blockIdx.y - 1;
        unsigned char* dstb = g_kv + (size_t)bat * (64 * 32768);
        for (int i = tid; i < 128 * 16; i += 256) {
            int r = i >> 4, ch = i & 15;          // 16B chunk 0-15 (256B row)
            int nl = n0 + r;
            int jt = nl >> 6, rl = nl & 63;
            int sub = ch >> 3;
            uint32_t off = (uint32_t)jt * 32768u + (uint32_t)kv * 16384u
                         + (uint32_t)sub * 8192u + (uint32_t)rl * 128u
                         + ((((uint32_t)rl & 7u) * 16u) ^ (((uint32_t)ch & 7u) * 16u));
            *(uint4*)(dstb + off) = *(const uint4*)(As + r * GP + ch * 8);
        }
    }
}

// ---------------------------------------------------------------------------
// Kernel 3: flash attention — K/V via cp.async.bulk (32KB/tile, 3-stage
// mbarrier ring), bf16 HMMA, register P, fused proj + residual epilogue.
// CTA = (q-tile 128, batch). 8 warps.
// ---------------------------------------------------------------------------
#define TQ 128
#define TKEY 64
#define QP 136
#define QBYTES (TQ * QP * 2)               // 34816
#define STB 32768
#define ST_OFF(s) (QBYTES + (s) * STB)
#define WB_OFF (QBYTES + 3 * STB)          // 133120
#define MB_OFF (WB_OFF + 128 * GP * 2)     // 167936
#define ATTN_SMEM (MB_OFF + 64)
#define OFP 132                            // fp32 epilogue pitch

__global__ __launch_bounds__(256, 1) void attn_kernel(const float* __restrict__ pw,
                                                      const float* __restrict__ pb,
                                                      const float* __restrict__ x,
                                                      float* __restrict__ y)
{
    extern __shared__ char sbc[];
    __nv_bfloat16* sb = (__nv_bfloat16*)sbc;
    const uint32_t sbase = (uint32_t)__cvta_generic_to_shared(sbc);
    const int tid = threadIdx.x;
    const int w = tid >> 5, lane = tid & 31;
    const int gid = lane >> 2, tig = lane & 3;
    const int qrow = w * 16 + gid;
    const int b = blockIdx.y;
    const int n0 = blockIdx.x * TQ;
    const __nv_bfloat16* Qg = g_q + (size_t)b * NTOK * C;
    const unsigned char* KVg = g_kv + (size_t)b * (64 * 32768);
    const uint32_t mbar = sbase + MB_OFF;

    if (tid == 0) {
        MBAR_INIT(mbar + 0, 1);
        MBAR_INIT(mbar + 8, 1);
        MBAR_INIT(mbar + 16, 1);
        MBAR_EXPECT_TX(mbar + 0, STB);
        bulkcp(sbase + ST_OFF(0), KVg, STB, mbar + 0);
        MBAR_EXPECT_TX(mbar + 8, STB);
        bulkcp(sbase + ST_OFF(1), KVg + STB, STB, mbar + 8);
    }

    // Q tile + W_proj, overlapped with first bulk copies
    for (int i = tid; i < TQ * 16; i += 256) {
        int r = i >> 4, c8 = (i & 15) << 3;
        *(uint4*)(sb + r * QP + c8) = *(const uint4*)(Qg + (size_t)(n0 + r) * C + c8);
    }
    __nv_bfloat16* Ws = (__nv_bfloat16*)(sbc + WB_OFF);
    for (int i = tid; i < 128 * 32; i += 256) {
        int r = i >> 5, c4 = (i & 31) << 2;
        float4 v = *(const float4*)(pw + (size_t)r * C + c4);
        *(uint32_t*)(Ws + r * GP + c4)     = pack_bf2(v.x, v.y);
        *(uint32_t*)(Ws + r * GP + c4 + 2) = pack_bf2(v.z, v.w);
    }
    __syncthreads();   // barrier init + smem fills visible

    const int l15 = lane & 15;
    const int hi8 = (lane >> 4) << 3;
    const uint32_t aQ = sbase + ((w * 16 + l15) * QP + hi8) * 2;
    const int vrow = (lane & 7) + ((lane >> 3) & 1) * 8;

    float oacc[16][4];
#pragma unroll
    for (int i = 0; i < 16; i++)
#pragma unroll
        for (int j = 0; j < 4; j++) oacc[i][j] = 0.f;
    float l0 = 0.f, l1 = 0.f;

    const int NT = NTOK / TKEY;
    for (int jt = 0; jt < NT; jt++) {
        const int s = jt % 3;
        MBAR_WAIT(mbar + 8 * s, (jt / 3) & 1);
        __syncthreads();                     // stage (jt+2)%3 fully consumed
        if (jt + 2 < NT && tid == 0) {
            const int s2 = (jt + 2) % 3;
            MBAR_EXPECT_TX(mbar + 8 * s2, STB);
            bulkcp(sbase + ST_OFF(s2), KVg + (size_t)(jt + 2) * STB, STB,
                   mbar + 8 * s2);
        }

        const uint32_t stK = sbase + ST_OFF(s);
        const uint32_t stV = stK + 16384;

        // ---- S = Q K^T (logits in log2 units) ----
        float sacc[8][4];
#pragma unroll
        for (int i = 0; i < 8; i++)
#pragma unroll
            for (int j = 0; j < 4; j++) sacc[i][j] = 0.f;

#pragma unroll
        for (int kk = 0; kk < 8; kk++) {
            const int k0 = kk * 16;
            uint32_t aq[4];
            LDSM4(aq, aQ + k0 * 2);
            const uint32_t sub = (k0 >= 64) ? 8192u : 0u;
            const uint32_t colb = (uint32_t)(((k0 & 63) + hi8) * 2);
#pragma unroll
            for (int ntp = 0; ntp < 4; ntp++) {
                const uint32_t row = (uint32_t)(ntp * 16 + l15);
                uint32_t bk[4];
                LDSM4(bk, stK + sub + row * 128u + (((row & 7u) * 16u) ^ colb));
                mma_bf16(sacc[2 * ntp],     aq, bk[0], bk[2]);
                mma_bf16(sacc[2 * ntp + 1], aq, bk[1], bk[3]);
            }
        }

        // ---- fused softmax (ex2) + O-MMA ----
#pragma unroll
        for (int kk = 0; kk < 4; kk++) {
            uint32_t ap[4];
            {
                float p0 = ex2f(sacc[2 * kk][0]);
                float p1 = ex2f(sacc[2 * kk][1]);
                float p2 = ex2f(sacc[2 * kk][2]);
                float p3 = ex2f(sacc[2 * kk][3]);
                l0 += p0 + p1; l1 += p2 + p3;
                ap[0] = pack_bf2(p0, p1);
                ap[1] = pack_bf2(p2, p3);
                float q0 = ex2f(sacc[2 * kk + 1][0]);
                float q1 = ex2f(sacc[2 * kk + 1][1]);
                float q2 = ex2f(sacc[2 * kk + 1][2]);
                float q3 = ex2f(sacc[2 * kk + 1][3]);
                l0 += q0 + q1; l1 += q2 + q3;
                ap[2] = pack_bf2(q0, q1);
                ap[3] = pack_bf2(q2, q3);
            }
            const uint32_t rowb = (uint32_t)(kk * 16 + vrow);
            const uint32_t rxor = (rowb & 7u) * 16u;
#pragma unroll
            for (int ccp = 0; ccp < 8; ccp++) {
                const int cc = ccp * 16 + hi8;
                const uint32_t sub = (cc >= 64) ? 8192u : 0u;
                const uint32_t colb = (uint32_t)((cc & 63) * 2);
                uint32_t bv[4];
                LDSM4T(bv, stV + sub + rowb * 128u + (rxor ^ colb));
                mma_bf16(oacc[2 * ccp],     ap, bv[0], bv[1]);
                mma_bf16(oacc[2 * ccp + 1], ap, bv[2], bv[3]);
            }
        }
    }
    __syncthreads();   // all stages consumed

    // ---- finalize O into Q smem region (bf16) ----
    l0 += __shfl_xor_sync(0xffffffffu, l0, 1);
    l0 += __shfl_xor_sync(0xffffffffu, l0, 2);
    l1 += __shfl_xor_sync(0xffffffffu, l1, 1);
    l1 += __shfl_xor_sync(0xffffffffu, l1, 2);
    float inv0 = 1.f / l0, inv1 = 1.f / l1;

#pragma unroll
    for (int nt = 0; nt < 16; nt++) {
        int col = nt * 8 + 2 * tig;
        *(uint32_t*)(sb + qrow * QP + col) =
            pack_bf2(oacc[nt][0] * inv0, oacc[nt][1] * inv0);
        *(uint32_t*)(sb + (qrow + 8) * QP + col) =
            pack_bf2(oacc[nt][2] * inv1, oacc[nt][3] * inv1);
    }
    __syncthreads();

    // ---- fused proj: acc = O @ Wp^T ----
    const uint32_t aW = sbase + WB_OFF + (l15 * GP + hi8) * 2;

    float acc[16][4];
#pragma unroll
    for (int i = 0; i < 16; i++)
#pragma unroll
        for (int j = 0; j < 4; j++) acc[i][j] = 0.f;

#pragma unroll
    for (int kk = 0; kk < 8; kk++) {
        const int k0 = kk * 16;
        uint32_t aq[4];
        LDSM4(aq, aQ + k0 * 2);            // O lives in Q region
#pragma unroll
        for (int ntp = 0; ntp < 8; ntp++) {
            uint32_t bk[4];
            LDSM4(bk, aW + (ntp * 16 * GP + k0) * 2);
            mma_bf16(acc[2 * ntp],     aq, bk[0], bk[2]);
            mma_bf16(acc[2 * ntp + 1], aq, bk[1], bk[3]);
        }
    }

    // ---- stage proj result fp32 [o][n] into retired stage region ----
    float* Ofp = (float*)(sbc + ST_OFF(0));    // pitch OFP, 128 rows (67.6KB)
    const int nl = w * 16 + gid;
#pragma unroll
    for (int nt = 0; nt < 16; nt++) {
        int o = nt * 8 + 2 * tig;
        Ofp[o * OFP + nl]           = acc[nt][0];
        Ofp[(o + 1) * OFP + nl]     = acc[nt][1];
        Ofp[o * OFP + nl + 8]       = acc[nt][2];
        Ofp[(o + 1) * OFP + nl + 8] = acc[nt][3];
    }
    __syncthreads();

    // ---- coalesced residual add + store: y = x + proj + pb ----
    for (int i = tid; i < 128 * 32; i += 256) {
        int o = i >> 5, n4 = (i & 31) << 2;
        size_t gaddr = ((size_t)b * C + o) * NTOK + n0 + n4;
        float4 xv = *(const float4*)(x + gaddr);
        float4 ov = *(const float4*)(Ofp + o * OFP + n4);
        float bo = pb[o];
        float4 r = make_float4(xv.x + ov.x + bo, xv.y + ov.y + bo,
                               xv.z + ov.z + bo, xv.w + ov.w + bo);
        *(float4*)(y + gaddr) = r;
    }
}

// ---------------------------------------------------------------------------
extern "C" void kernel_launch(void* const* d_in, const int* in_sizes, int n_in,
                              void* d_out, int out_size)
{
    const float* x     = (const float*)d_in[0];
    const float* gn_w  = (const float*)d_in[1];
    const float* gn_b  = (const float*)d_in[2];
    const float* qkv_w = (const float*)d_in[3];
    const float* qkv_b = (const float*)d_in[4];
    const float* pr_w  = (const float*)d_in[5];
    const float* pr_b  = (const float*)d_in[6];
    float* y = (float*)d_out;

    cudaFuncSetAttribute(qkv_kernel,  cudaFuncAttributeMaxDynamicSharedMemorySize, QKV_SMEM);
    cudaFuncSetAttribute(attn_kernel, cudaFuncAttributeMaxDynamicSharedMemorySize, ATTN_SMEM);

    gn_stats_kernel<<<BATCH * NG * 16, 256>>>(x);
    qkv_kernel<<<dim3((BATCH * NTOK) / 128, 3), 256, QKV_SMEM>>>(x, gn_w, gn_b, qkv_w, qkv_b);
    attn_kernel<<<dim3(NTOK / TQ, BATCH), 256, ATTN_SMEM>>>(pr_w, pr_b, x, y);
}

// round 13
// speedup vs baseline: 1.2924x; 1.1123x over previous
#include <cuda_runtime.h>
#include <cuda_bf16.h>
#include <math.h>
#include <cstdint>

// Problem constants
#define BATCH 4
#define C 128
#define NG 8
#define CPG 16
#define NTOK 4096
#define EPS 1e-5f
#define QSCALE (0.08838834764831845f * 1.4426950408889634f)  // 1/sqrt(C) * log2(e)

// Scratch
__device__ float2        g_part[BATCH * NG * 16];     // partial (sum, sumsq)
__device__ unsigned char g_kv[BATCH * 64 * 32768];    // swizzled 32KB K/V tiles
__device__ unsigned int  g_flag[BATCH];               // per-batch barrier

// ---------------------------------------------------------------------------
// helpers
// ---------------------------------------------------------------------------
__device__ __forceinline__ void mma_bf16(float* d, const uint32_t* a,
                                         uint32_t b0, uint32_t b1) {
    asm volatile(
        "mma.sync.aligned.m16n8k16.row.col.f32.bf16.bf16.f32 "
        "{%0,%1,%2,%3}, {%4,%5,%6,%7}, {%8,%9}, {%0,%1,%2,%3};"
        : "+f"(d[0]), "+f"(d[1]), "+f"(d[2]), "+f"(d[3])
        : "r"(a[0]), "r"(a[1]), "r"(a[2]), "r"(a[3]), "r"(b0), "r"(b1));
}
#define LDSM4(R, A) \
    asm volatile("ldmatrix.sync.aligned.m8n8.x4.shared.b16 {%0,%1,%2,%3}, [%4];" \
        : "=r"((R)[0]), "=r"((R)[1]), "=r"((R)[2]), "=r"((R)[3]) : "r"(A))
#define LDSM4T(R, A) \
    asm volatile("ldmatrix.sync.aligned.m8n8.x4.trans.shared.b16 {%0,%1,%2,%3}, [%4];" \
        : "=r"((R)[0]), "=r"((R)[1]), "=r"((R)[2]), "=r"((R)[3]) : "r"(A))
__device__ __forceinline__ uint32_t pack_bf2(float a, float b) {
    __nv_bfloat162 h = __floats2bfloat162_rn(a, b);
    return *reinterpret_cast<uint32_t*>(&h);
}
__device__ __forceinline__ float ex2f(float x) {
    float r;
    asm("ex2.approx.f32 %0, %1;" : "=f"(r) : "f"(x));
    return r;
}
__device__ __forceinline__ void bulkcp(uint32_t dst, const void* src,
                                       uint32_t bytes, uint32_t mbar) {
    asm volatile(
        "cp.async.bulk.shared::cta.global.mbarrier::complete_tx::bytes "
        "[%0], [%1], %2, [%3];"
        :: "r"(dst), "l"(src), "r"(bytes), "r"(mbar) : "memory");
}
#define MBAR_INIT(a, n) \
    asm volatile("mbarrier.init.shared.b64 [%0], %1;" :: "r"(a), "r"(n) : "memory")
#define MBAR_EXPECT_TX(a, n) \
    asm volatile("mbarrier.arrive.expect_tx.shared.b64 _, [%0], %1;" \
                 :: "r"(a), "r"(n) : "memory")
#define MBAR_WAIT(addr, parity) do { \
    asm volatile("{\n\t.reg .pred P1;\n\t" \
        "WAIT_%=:\n\t" \
        "mbarrier.try_wait.parity.acquire.cta.shared::cta.b64 P1, [%0], %1, 0x989680;\n\t" \
        "@P1 bra.uni DONE_%=;\n\t" \
        "bra.uni WAIT_%=;\n\t" \
        "DONE_%=:\n\t}" \
        :: "r"(addr), "r"(parity) : "memory"); \
} while (0)

// ---------------------------------------------------------------------------
// Kernel 1: GroupNorm partial stats + barrier-flag reset. Grid 512.
// ---------------------------------------------------------------------------
__global__ void gn_stats_kernel(const float* __restrict__ x)
{
    if (blockIdx.x < BATCH && threadIdx.x == 0) g_flag[blockIdx.x] = 0;

    int bg = blockIdx.x >> 4, ck = blockIdx.x & 15;
    const float4* xp = (const float4*)(x + (size_t)bg * CPG * NTOK
                                         + (size_t)ck * (CPG * NTOK / 16));
    int t = threadIdx.x;
    float s = 0.f, ss = 0.f;
#pragma unroll
    for (int i = 0; i < 4; i++) {
        float4 v = xp[t + i * 256];
        s  += v.x + v.y + v.z + v.w;
        ss += v.x * v.x + v.y * v.y + v.z * v.z + v.w * v.w;
    }
#pragma unroll
    for (int o = 16; o > 0; o >>= 1) {
        s  += __shfl_xor_sync(0xffffffffu, s, o);
        ss += __shfl_xor_sync(0xffffffffu, ss, o);
    }
    __shared__ float rs[8], rss[8];
    if ((t & 31) == 0) { rs[t >> 5] = s; rss[t >> 5] = ss; }
    __syncthreads();
    if (t == 0) {
        float a = 0.f, b = 0.f;
#pragma unroll
        for (int i = 0; i < 8; i++) { a += rs[i]; b += rss[i]; }
        g_part[blockIdx.x] = make_float2(a, b);
    }
}

// ---------------------------------------------------------------------------
// Kernel 2: MEGA kernel — GN-normalize + QKV GEMM (phase 1), per-batch
// global barrier, flash attention + fused proj + residual (phase 2).
// Grid (32 q-tiles, 4 batches) = 128 CTAs, 1 wave, all co-resident.
// ---------------------------------------------------------------------------
#define GP 136
#define QP 136
#define TQ 128
#define TKEY 64
#define QBYTES (TQ * QP * 2)               // 34816  (Q / staging region, off 0)
#define STB 32768
#define ST_OFF(s) (QBYTES + (s) * STB)     // 3 stages
#define WB_OFF (QBYTES + 3 * STB)          // 133120 (As in ph1, W_proj in ph2)
#define MB_OFF (WB_OFF + 128 * GP * 2)     // 167936
#define ATTN_SMEM (MB_OFF + 64)
#define OFP 132

__global__ __launch_bounds__(256, 1) void mega_kernel(const float* __restrict__ x,
                                                      const float* __restrict__ gnw,
                                                      const float* __restrict__ gnb,
                                                      const float* __restrict__ W,
                                                      const float* __restrict__ bias,
                                                      const float* __restrict__ pw,
                                                      const float* __restrict__ pb,
                                                      float* __restrict__ y)
{
    extern __shared__ char sbc[];
    __nv_bfloat16* sb = (__nv_bfloat16*)sbc;
    const uint32_t sbase = (uint32_t)__cvta_generic_to_shared(sbc);
    const int tid = threadIdx.x;
    const int w = tid >> 5, lane = tid & 31;
    const int gid = lane >> 2, tig = lane & 3;
    const int qrow = w * 16 + gid;
    const int b = blockIdx.y;
    const int n0 = blockIdx.x * TQ;
    const uint32_t mbar = sbase + MB_OFF;

    // ============ PHASE 1: GroupNorm-normalize + QKV GEMM ============
    __shared__ float stats[16];
    if (tid < 8) {
        float s = 0.f, ss = 0.f;
#pragma unroll
        for (int ck = 0; ck < 16; ck++) {
            float2 p = g_part[(b * NG + tid) * 16 + ck];
            s += p.x; ss += p.y;
        }
        float mean = s * (1.f / (CPG * NTOK));
        float var  = ss * (1.f / (CPG * NTOK)) - mean * mean;
        stats[tid * 2]     = mean;
        stats[tid * 2 + 1] = rsqrtf(var + EPS);
    }
    __syncthreads();

    // As (c-major [c][m], pitch GP) in WB region — x read once, normalized
    __nv_bfloat16* As = (__nv_bfloat16*)(sbc + WB_OFF);
    for (int i = tid; i < 128 * 32; i += 256) {
        int c = i >> 5, n4 = (i & 31) << 2;
        float4 v = *(const float4*)(x + ((size_t)b * C + c) * NTOK + n0 + n4);
        int g = c >> 4;
        float a = stats[g * 2 + 1] * gnw[c];
        float bb = gnb[c] - stats[g * 2] * a;
        *(uint32_t*)(As + c * GP + n4)     = pack_bf2(v.x * a + bb, v.y * a + bb);
        *(uint32_t*)(As + c * GP + n4 + 2) = pack_bf2(v.z * a + bb, v.w * a + bb);
    }

    const int l15 = lane & 15;
    const int hi8 = (lane >> 4) << 3;
    const int arow = (lane & 7) + ((lane >> 4) << 3);
    const int acol = ((lane >> 3) & 1) << 3;
    const uint32_t aA = sbase + WB_OFF + (arow * GP + w * 16 + acol) * 2;
    __nv_bfloat16* Bs = (__nv_bfloat16*)(sbc + ST_OFF(0));   // spans into stage1
    const uint32_t aB = sbase + ST_OFF(0) + (l15 * GP + hi8) * 2;
    const int ml = w * 16 + gid;
    unsigned char* dstb = g_kv + (size_t)b * (64 * 32768);

    // o-block order: K(1), V(2), Q(0) — Q output stays resident in Q region
    const int obs[3] = {1, 2, 0};
#pragma unroll 1
    for (int oi = 0; oi < 3; oi++) {
        const int ob = obs[oi];
        const int o0 = ob * 128;
        for (int i = tid; i < 128 * 32; i += 256) {
            int r = i >> 5, c4 = (i & 31) << 2;
            float4 v = *(const float4*)(W + (size_t)(o0 + r) * C + c4);
            *(uint32_t*)(Bs + r * GP + c4)     = pack_bf2(v.x, v.y);
            *(uint32_t*)(Bs + r * GP + c4 + 2) = pack_bf2(v.z, v.w);
        }
        __syncthreads();

        float acc[16][4];
#pragma unroll
        for (int i = 0; i < 16; i++)
#pragma unroll
            for (int j = 0; j < 4; j++) acc[i][j] = 0.f;

#pragma unroll
        for (int kk = 0; kk < 8; kk++) {
            const int k0 = kk * 16;
            uint32_t aq[4];
            LDSM4T(aq, aA + k0 * GP * 2);
#pragma unroll
            for (int ntp = 0; ntp < 8; ntp++) {
                uint32_t bk[4];
                LDSM4(bk, aB + (ntp * 16 * GP + k0) * 2);
                mma_bf16(acc[2 * ntp],     aq, bk[0], bk[2]);
                mma_bf16(acc[2 * ntp + 1], aq, bk[1], bk[3]);
            }
        }
        __syncthreads();   // Bs consumed; staging region free

        // stage bf16 [m][o] into Q region
        const float sc = (ob == 0) ? QSCALE : 1.f;
#pragma unroll
        for (int nt = 0; nt < 16; nt++) {
            int o = nt * 8 + 2 * tig;
            float b0 = bias[o0 + o], b1 = bias[o0 + o + 1];
            *(uint32_t*)(sb + ml * QP + o) =
                pack_bf2((acc[nt][0] + b0) * sc, (acc[nt][1] + b1) * sc);
            *(uint32_t*)(sb + (ml + 8) * QP + o) =
                pack_bf2((acc[nt][2] + b0) * sc, (acc[nt][3] + b1) * sc);
        }
        __syncthreads();

        if (ob != 0) {
            // coalesced swizzled K/V tile write
            const int kv = ob - 1;
            for (int i = tid; i < 128 * 16; i += 256) {
                int r = i >> 4, ch = i & 15;
                int nl = n0 + r;
                int jt = nl >> 6, rl = nl & 63;
                int sub = ch >> 3;
                uint32_t off = (uint32_t)jt * 32768u + (uint32_t)kv * 16384u
                             + (uint32_t)sub * 8192u + (uint32_t)rl * 128u
                             + ((((uint32_t)rl & 7u) * 16u) ^ (((uint32_t)ch & 7u) * 16u));
                *(uint4*)(dstb + off) = *(const uint4*)(sb + r * QP + ch * 8);
            }
            __syncthreads();   // staging reusable
        }
    }

    // load W_proj into WB (As no longer needed); init mbarriers
    __nv_bfloat16* Ws = (__nv_bfloat16*)(sbc + WB_OFF);
    for (int i = tid; i < 128 * 32; i += 256) {
        int r = i >> 5, c4 = (i & 31) << 2;
        float4 v = *(const float4*)(pw + (size_t)r * C + c4);
        *(uint32_t*)(Ws + r * GP + c4)     = pack_bf2(v.x, v.y);
        *(uint32_t*)(Ws + r * GP + c4 + 2) = pack_bf2(v.z, v.w);
    }
    if (tid == 0) {
        MBAR_INIT(mbar + 0, 1);
        MBAR_INIT(mbar + 8, 1);
        MBAR_INIT(mbar + 16, 1);
    }
    __syncthreads();

    // ============ per-batch global barrier (32 CTAs) ============
    if (tid == 0) {
        asm volatile("red.release.gpu.global.add.u32 [%0], 1;"
                     :: "l"(&g_flag[b]) : "memory");
        unsigned v;
        do {
            asm volatile("ld.acquire.gpu.global.u32 %0, [%1];"
                         : "=r"(v) : "l"(&g_flag[b]) : "memory");
        } while (v < 32);
    }
    __syncthreads();
    asm volatile("fence.proxy.async;" ::: "memory");

    // ============ PHASE 2: flash attention + fused proj ============
    const unsigned char* KVg = dstb;
    if (tid == 0) {
        MBAR_EXPECT_TX(mbar + 0, STB);
        bulkcp(sbase + ST_OFF(0), KVg, STB, mbar + 0);
        MBAR_EXPECT_TX(mbar + 8, STB);
        bulkcp(sbase + ST_OFF(1), KVg + STB, STB, mbar + 8);
    }

    const uint32_t aQ = sbase + ((w * 16 + l15) * QP + hi8) * 2;
    const int vrow = (lane & 7) + ((lane >> 3) & 1) * 8;

    float oacc[16][4];
#pragma unroll
    for (int i = 0; i < 16; i++)
#pragma unroll
        for (int j = 0; j < 4; j++) oacc[i][j] = 0.f;
    float l0 = 0.f, l1 = 0.f;

    const int NT = NTOK / TKEY;
    for (int jt = 0; jt < NT; jt++) {
        const int s = jt % 3;
        MBAR_WAIT(mbar + 8 * s, (jt / 3) & 1);
        __syncthreads();
        if (jt + 2 < NT && tid == 0) {
            const int s2 = (jt + 2) % 3;
            MBAR_EXPECT_TX(mbar + 8 * s2, STB);
            bulkcp(sbase + ST_OFF(s2), KVg + (size_t)(jt + 2) * STB, STB,
                   mbar + 8 * s2);
        }

        const uint32_t stK = sbase + ST_OFF(s);
        const uint32_t stV = stK + 16384;

        float sacc[8][4];
#pragma unroll
        for (int i = 0; i < 8; i++)
#pragma unroll
            for (int j = 0; j < 4; j++) sacc[i][j] = 0.f;

#pragma unroll
        for (int kk = 0; kk < 8; kk++) {
            const int k0 = kk * 16;
            uint32_t aq[4];
            LDSM4(aq, aQ + k0 * 2);
            const uint32_t sub = (k0 >= 64) ? 8192u : 0u;
            const uint32_t colb = (uint32_t)(((k0 & 63) + hi8) * 2);
#pragma unroll
            for (int ntp = 0; ntp < 4; ntp++) {
                const uint32_t row = (uint32_t)(ntp * 16 + l15);
                uint32_t bk[4];
                LDSM4(bk, stK + sub + row * 128u + (((row & 7u) * 16u) ^ colb));
                mma_bf16(sacc[2 * ntp],     aq, bk[0], bk[2]);
                mma_bf16(sacc[2 * ntp + 1], aq, bk[1], bk[3]);
            }
        }

#pragma unroll
        for (int kk = 0; kk < 4; kk++) {
            uint32_t ap[4];
            {
                float p0 = ex2f(sacc[2 * kk][0]);
                float p1 = ex2f(sacc[2 * kk][1]);
                float p2 = ex2f(sacc[2 * kk][2]);
                float p3 = ex2f(sacc[2 * kk][3]);
                l0 += p0 + p1; l1 += p2 + p3;
                ap[0] = pack_bf2(p0, p1);
                ap[1] = pack_bf2(p2, p3);
                float q0 = ex2f(sacc[2 * kk + 1][0]);
                float q1 = ex2f(sacc[2 * kk + 1][1]);
                float q2 = ex2f(sacc[2 * kk + 1][2]);
                float q3 = ex2f(sacc[2 * kk + 1][3]);
                l0 += q0 + q1; l1 += q2 + q3;
                ap[2] = pack_bf2(q0, q1);
                ap[3] = pack_bf2(q2, q3);
            }
            const uint32_t rowb = (uint32_t)(kk * 16 + vrow);
            const uint32_t rxor = (rowb & 7u) * 16u;
#pragma unroll
            for (int ccp = 0; ccp < 8; ccp++) {
                const int cc = ccp * 16 + hi8;
                const uint32_t sub = (cc >= 64) ? 8192u : 0u;
                const uint32_t colb = (uint32_t)((cc & 63) * 2);
                uint32_t bv[4];
                LDSM4T(bv, stV + sub + rowb * 128u + (rxor ^ colb));
                mma_bf16(oacc[2 * ccp],     ap, bv[0], bv[1]);
                mma_bf16(oacc[2 * ccp + 1], ap, bv[2], bv[3]);
            }
        }
    }
    __syncthreads();

    // ---- finalize O into Q smem region (bf16) ----
    l0 += __shfl_xor_sync(0xffffffffu, l0, 1);
    l0 += __shfl_xor_sync(0xffffffffu, l0, 2);
    l1 += __shfl_xor_sync(0xffffffffu, l1, 1);
    l1 += __shfl_xor_sync(0xffffffffu, l1, 2);
    float inv0 = 1.f / l0, inv1 = 1.f / l1;

#pragma unroll
    for (int nt = 0; nt < 16; nt++) {
        int col = nt * 8 + 2 * tig;
        *(uint32_t*)(sb + qrow * QP + col) =
            pack_bf2(oacc[nt][0] * inv0, oacc[nt][1] * inv0);
        *(uint32_t*)(sb + (qrow + 8) * QP + col) =
            pack_bf2(oacc[nt][2] * inv1, oacc[nt][3] * inv1);
    }
    __syncthreads();

    // ---- fused proj: acc = O @ Wp^T ----
    const uint32_t aW = sbase + WB_OFF + (l15 * GP + hi8) * 2;

    float acc[16][4];
#pragma unroll
    for (int i = 0; i < 16; i++)
#pragma unroll
        for (int j = 0; j < 4; j++) acc[i][j] = 0.f;

#pragma unroll
    for (int kk = 0; kk < 8; kk++) {
        const int k0 = kk * 16;
        uint32_t aq[4];
        LDSM4(aq, aQ + k0 * 2);
#pragma unroll
        for (int ntp = 0; ntp < 8; ntp++) {
            uint32_t bk[4];
            LDSM4(bk, aW + (ntp * 16 * GP + k0) * 2);
            mma_bf16(acc[2 * ntp],     aq, bk[0], bk[2]);
            mma_bf16(acc[2 * ntp + 1], aq, bk[1], bk[3]);
        }
    }

    // ---- stage proj fp32 [o][n] into stage region ----
    float* Ofp = (float*)(sbc + ST_OFF(0));
    const int nl = w * 16 + gid;
#pragma unroll
    for (int nt = 0; nt < 16; nt++) {
        int o = nt * 8 + 2 * tig;
        Ofp[o * OFP + nl]           = acc[nt][0];
        Ofp[(o + 1) * OFP + nl]     = acc[nt][1];
        Ofp[o * OFP + nl + 8]       = acc[nt][2];
        Ofp[(o + 1) * OFP + nl + 8] = acc[nt][3];
    }
    __syncthreads();

    // ---- coalesced residual add + store ----
    for (int i = tid; i < 128 * 32; i += 256) {
        int o = i >> 5, n4 = (i & 31) << 2;
        size_t gaddr = ((size_t)b * C + o) * NTOK + n0 + n4;
        float4 xv = *(const float4*)(x + gaddr);
        float4 ov = *(const float4*)(Ofp + o * OFP + n4);
        float bo = pb[o];
        float4 r = make_float4(xv.x + ov.x + bo, xv.y + ov.y + bo,
                               xv.z + ov.z + bo, xv.w + ov.w + bo);
        *(float4*)(y + gaddr) = r;
    }
}

// ---------------------------------------------------------------------------
extern "C" void kernel_launch(void* const* d_in, const int* in_sizes, int n_in,
                              void* d_out, int out_size)
{
    const float* x     = (const float*)d_in[0];
    const float* gn_w  = (const float*)d_in[1];
    const float* gn_b  = (const float*)d_in[2];
    const float* qkv_w = (const float*)d_in[3];
    const float* qkv_b = (const float*)d_in[4];
    const float* pr_w  = (const float*)d_in[5];
    const float* pr_b  = (const float*)d_in[6];
    float* y = (float*)d_out;

    cudaFuncSetAttribute(mega_kernel, cudaFuncAttributeMaxDynamicSharedMemorySize,
                         ATTN_SMEM);

    gn_stats_kernel<<<BATCH * NG * 16, 256>>>(x);
    mega_kernel<<<dim3(NTOK / TQ, BATCH), 256, ATTN_SMEM>>>(
        x, gn_w, gn_b, qkv_w, qkv_b, pr_w, pr_b, y);
}